// round 7
// baseline (speedup 1.0000x reference)
#include <cuda_runtime.h>
#include <cuda_bf16.h>
#include <cstdint>

#define NN 50000
#define NE 800000
#define DIM 256
#define RB 391   // ceil(NN/128)

typedef unsigned long long ull;

// ---------------- global scratch ----------------
__device__ __align__(16) float g_z[NN * DIM];          // aggr; later pre-LN h (zeroed by k_ln)
__device__ __align__(128) char g_weH[32768];           // We image  [64k][256n] bf16 hi
__device__ __align__(128) char g_weL[32768];
__device__ __align__(128) char g_w1H[131072];          // W1 images, 4 chunks x 32KB
__device__ __align__(128) char g_w1L[131072];
__device__ __align__(128) char g_w2H[131072];
__device__ __align__(128) char g_w2L[131072];
__device__ __align__(128) char g_h1H[RB * 65536];      // h1 A-images (per rowblock, 4 kc x 16KB)
__device__ __align__(128) char g_h1L[RB * 65536];

// ---------------- helpers ----------------
template <int S>
__device__ __forceinline__ uint32_t swz(uint32_t off) {
    return off ^ (((off >> S) & 7u) << 4);
}
// column-pair permutation so MMA C-fragments give 4 consecutive logical cols
__device__ __forceinline__ int permp(int np) {
    return (np & ~7) | ((np & 7) >> 1) | ((np & 1) << 2);
}
__device__ __forceinline__ uint32_t smem_u32(const void* p) {
    uint32_t a;
    asm("{ .reg .u64 t; cvta.to.shared.u64 t, %1; cvt.u32.u64 %0, t; }" : "=r"(a) : "l"(p));
    return a;
}
__device__ __forceinline__ void ldsm4(uint32_t r[4], uint32_t a) {
    asm volatile("ldmatrix.sync.aligned.m8n8.x4.shared.b16 {%0,%1,%2,%3}, [%4];"
                 : "=r"(r[0]), "=r"(r[1]), "=r"(r[2]), "=r"(r[3]) : "r"(a));
}
__device__ __forceinline__ void ldsm4t(uint32_t r[4], uint32_t a) {
    asm volatile("ldmatrix.sync.aligned.m8n8.x4.trans.shared.b16 {%0,%1,%2,%3}, [%4];"
                 : "=r"(r[0]), "=r"(r[1]), "=r"(r[2]), "=r"(r[3]) : "r"(a));
}
__device__ __forceinline__ void mma16816(float d[4], const uint32_t a[4], const uint32_t b[2]) {
    asm volatile("mma.sync.aligned.m16n8k16.row.col.f32.bf16.bf16.f32 "
                 "{%0,%1,%2,%3}, {%4,%5,%6,%7}, {%8,%9}, {%0,%1,%2,%3};"
                 : "+f"(d[0]), "+f"(d[1]), "+f"(d[2]), "+f"(d[3])
                 : "r"(a[0]), "r"(a[1]), "r"(a[2]), "r"(a[3]), "r"(b[0]), "r"(b[1]));
}
__device__ __forceinline__ void red4(float* a, float4 v) {
    asm volatile("red.global.add.v4.f32 [%0], {%1,%2,%3,%4};"
                 :: "l"(a), "f"(v.x), "f"(v.y), "f"(v.z), "f"(v.w));
}
__device__ __forceinline__ void cpa16(uint32_t dst, const void* src) {
    asm volatile("cp.async.cg.shared.global [%0], [%1], 16;" :: "r"(dst), "l"(src));
}
__device__ __forceinline__ void cpa_commit() { asm volatile("cp.async.commit_group;"); }
__device__ __forceinline__ void cpa_wait0()  { asm volatile("cp.async.wait_group 0;"); }
__device__ __forceinline__ void cpa_wait1()  { asm volatile("cp.async.wait_group 1;"); }

__device__ __forceinline__ void store_pair(char* bH, char* bL, uint32_t off, float2 v) {
    __nv_bfloat16 h0 = __float2bfloat16(v.x), h1 = __float2bfloat16(v.y);
    __nv_bfloat16 l0 = __float2bfloat16(v.x - __bfloat162float(h0));
    __nv_bfloat16 l1 = __float2bfloat16(v.y - __bfloat162float(h1));
    *(__nv_bfloat162*)(bH + off) = __halves2bfloat162(h0, h1);
    *(__nv_bfloat162*)(bL + off) = __halves2bfloat162(l0, l1);
}

// ---------------------------------------------------------------------------
// Mainloop chunk: acc += A[32 rows x 64k] @ B[64k x 64 cols] with 3-pass bf16
// split (Ah*Bh + Ah*Bl + Al*Bh). A: 128B rows swz<7>; B: 512B rows swz<9>.
// ---------------------------------------------------------------------------
__device__ __forceinline__ void mma_chunk(float acc[2][8][4],
    uint32_t aH, uint32_t aL, uint32_t bH, uint32_t bL,
    int mbase, int nbase, int l)
{
    const int lr = l & 7, lg8 = ((l >> 3) & 1) * 8, lh8 = (l >> 4) * 8;
    #pragma unroll
    for (int ks = 0; ks < 4; ks++) {
        uint32_t a[2][4], bh[8][2], bl[8][2];
        #pragma unroll
        for (int mf = 0; mf < 2; mf++)
            ldsm4(a[mf], aH + swz<7>((uint32_t)((mbase + mf * 16 + lr + lg8) * 128
                                                + (ks * 16 + lh8) * 2)));
        #pragma unroll
        for (int nq = 0; nq < 4; nq++) {
            uint32_t r4[4];
            uint32_t off = swz<9>((uint32_t)((ks * 16 + lr + lg8) * 512
                                             + (nbase + nq * 16 + lh8) * 2));
            ldsm4t(r4, bH + off);
            bh[2 * nq][0] = r4[0]; bh[2 * nq][1] = r4[1];
            bh[2 * nq + 1][0] = r4[2]; bh[2 * nq + 1][1] = r4[3];
            ldsm4t(r4, bL + off);
            bl[2 * nq][0] = r4[0]; bl[2 * nq][1] = r4[1];
            bl[2 * nq + 1][0] = r4[2]; bl[2 * nq + 1][1] = r4[3];
        }
        #pragma unroll
        for (int mf = 0; mf < 2; mf++)
            #pragma unroll
            for (int nf = 0; nf < 8; nf++)
                mma16816(acc[mf][nf], a[mf], bh[nf]);
        #pragma unroll
        for (int mf = 0; mf < 2; mf++)
            #pragma unroll
            for (int nf = 0; nf < 8; nf++)
                mma16816(acc[mf][nf], a[mf], bl[nf]);
        #pragma unroll
        for (int mf = 0; mf < 2; mf++)
            ldsm4(a[mf], aL + swz<7>((uint32_t)((mbase + mf * 16 + lr + lg8) * 128
                                                + (ks * 16 + lh8) * 2)));
        #pragma unroll
        for (int mf = 0; mf < 2; mf++)
            #pragma unroll
            for (int nf = 0; nf < 8; nf++)
                mma16816(acc[mf][nf], a[mf], bh[nf]);
    }
}

// ---------------------------------------------------------------------------
// k_prep: build bf16 hi/lo weight images (smem byte layout, swizzle+perm baked)
// ---------------------------------------------------------------------------
__global__ __launch_bounds__(256) void k_prep(const float* __restrict__ We,
                                              const float* __restrict__ W1,
                                              const float* __restrict__ W2)
{
    int i = blockIdx.x * 256 + threadIdx.x;
    if (i < 8192) {                       // We: 64k x 128 pairs
        int k = i >> 7, np = i & 127;
        uint32_t off = swz<9>((uint32_t)(k * 512 + permp(np) * 4));
        store_pair(g_weH, g_weL, off, ((const float2*)We)[i]);
    } else if (i < 40960) {               // W1: 4 chunks x 64k x 128 pairs
        int j = i - 8192;
        int kc = j >> 13, k = (j >> 7) & 63, np = j & 127;
        uint32_t off = (uint32_t)(kc * 32768) + swz<9>((uint32_t)(k * 512 + permp(np) * 4));
        store_pair(g_w1H, g_w1L, off, ((const float2*)W1)[j]);
    } else if (i < 73728) {               // W2
        int j = i - 40960;
        int kc = j >> 13, k = (j >> 7) & 63, np = j & 127;
        uint32_t off = (uint32_t)(kc * 32768) + swz<9>((uint32_t)(k * 512 + permp(np) * 4));
        store_pair(g_w2H, g_w2L, off, ((const float2*)W2)[j]);
    }
}

// ---------------------------------------------------------------------------
// k_edge: CTA = 128 edges x 256 cols, 512 threads (wm4 x wn4).
// x[src] rows prefetched to smem via cp.async, overlapped with the MMA.
// msg = relu(ea@We + x[src] + be) -> red.v4 into g_z[dst] (g_z starts zeroed).
// ---------------------------------------------------------------------------
#define E_AH  0
#define E_AL  16384
#define E_BH  32768
#define E_BL  65536
#define E_X   98304
#define E_IDX 229376
#define E_SMEM 230400

__global__ __launch_bounds__(512, 1) void k_edge(
    const float* __restrict__ x, const int* __restrict__ eidx,
    const float* __restrict__ ea, const float* __restrict__ be)
{
    extern __shared__ char sm[];
    const int t = threadIdx.x, w = t >> 5, l = t & 31;
    const int wm = w & 3, wn = w >> 2, j = l & 3;
    const uint32_t sb = smem_u32(sm);
    const long long e0 = (long long)blockIdx.x * 128;
    int* s_idx = (int*)(sm + E_IDX);

    // 1) edge indices -> smem
    if (t < 128) s_idx[t] = eidx[e0 + t];                 // src
    else if (t < 256) s_idx[t] = eidx[NE + e0 + t - 128]; // dst
    __syncthreads();

    // 2) group 0: B images (We)
    #pragma unroll
    for (int i0 = 0; i0 < 4; i0++) {
        int i = i0 * 512 + t;
        cpa16(sb + E_BH + i * 16, g_weH + i * 16);
        cpa16(sb + E_BL + i * 16, g_weL + i * 16);
    }
    cpa_commit();
    // 3) group 1: x[src] rows (128 x 1KB)
    #pragma unroll
    for (int i0 = 0; i0 < 16; i0++) {
        int i = i0 * 512 + t;
        int r = i >> 6, c4 = i & 63;
        cpa16(sb + E_X + r * 1024 + c4 * 16, x + (size_t)s_idx[r] * DIM + c4 * 4);
    }
    cpa_commit();

    // 4) A: convert edge_attr tile [128][64] to bf16 hi/lo
    const float2* ea2 = (const float2*)(ea + (size_t)blockIdx.x * (128 * 64));
    #pragma unroll
    for (int i0 = 0; i0 < 8; i0++) {
        int i = i0 * 512 + t;
        int r = i >> 5, kp = i & 31;
        store_pair(sm + E_AH, sm + E_AL, swz<7>((uint32_t)(r * 128 + kp * 4)), ea2[i]);
    }

    cpa_wait1();        // B landed (x may still stream)
    __syncthreads();

    float acc[2][8][4];
    #pragma unroll
    for (int mf = 0; mf < 2; mf++)
        #pragma unroll
        for (int nf = 0; nf < 8; nf++) {
            acc[mf][nf][0] = 0.f; acc[mf][nf][1] = 0.f;
            acc[mf][nf][2] = 0.f; acc[mf][nf][3] = 0.f;
        }
    mma_chunk(acc, sb + E_AH, sb + E_AL, sb + E_BH, sb + E_BL, wm * 32, wn * 64, l);

    cpa_wait0();        // x rows landed
    __syncthreads();

    // 5) epilogue: relu(acc + x + be) -> red.v4 (x read from smem, no L2 latency)
    #pragma unroll
    for (int mf = 0; mf < 2; mf++)
        #pragma unroll
        for (int rh = 0; rh < 2; rh++) {
            int r = wm * 32 + mf * 16 + rh * 8 + (l >> 2);
            float* zd = g_z + (size_t)s_idx[128 + r] * DIM;
            #pragma unroll
            for (int nq = 0; nq < 4; nq++) {
                int col = wn * 64 + nq * 16 + 4 * j;
                float4 xv = *(const float4*)(sm + E_X + r * 1024 + col * 4);
                float4 bv = ((const float4*)be)[col >> 2];
                float4 o;
                o.x = fmaxf(acc[mf][2 * nq][2 * rh]     + xv.x + bv.x, 0.f);
                o.y = fmaxf(acc[mf][2 * nq][2 * rh + 1] + xv.y + bv.y, 0.f);
                o.z = fmaxf(acc[mf][2 * nq + 1][2 * rh]     + xv.z + bv.z, 0.f);
                o.w = fmaxf(acc[mf][2 * nq + 1][2 * rh + 1] + xv.w + bv.w, 0.f);
                red4(zd + col, o);
            }
        }
}

// ---------------------------------------------------------------------------
// MLP kernels: 512 threads (wm 4 x wn 4), CTA = 128 rows x 256 cols,
// K=256 in 4 chunks, double-buffered cp.async for B (and A in mlp2).
// ---------------------------------------------------------------------------
#define P_A(buf)  ((buf) * 32768)              // A hi at 0 / 32768
#define P_AL(buf) ((buf) * 32768 + 16384)
#define P_B(buf)  (65536 + (buf) * 65536)      // B hi at 65536 / 131072
#define P_BL(buf) (65536 + (buf) * 65536 + 32768)
#define P_SMEM 196608

// Kernel 3: h1 = relu((x + g_z) @ W1 + b1) -> bf16 hi/lo A-images for mlp2
__global__ __launch_bounds__(512, 1) void k_mlp1(const float* __restrict__ x,
                                                 const float* __restrict__ b1)
{
    extern __shared__ char sm[];
    const int t = threadIdx.x, w = t >> 5, l = t & 31;
    const int wm = w & 3, wn = w >> 2, j = l & 3;
    const uint32_t sb = smem_u32(sm);
    const int rb = blockIdx.x, rowb = rb * 128;

    // prologue: B0 cp.async + A0 convert (z = x + aggr)
    #pragma unroll
    for (int i0 = 0; i0 < 4; i0++) {
        int i = i0 * 512 + t;
        cpa16(sb + P_B(0) + i * 16, g_w1H + i * 16);
        cpa16(sb + P_BL(0) + i * 16, g_w1L + i * 16);
    }
    cpa_commit();
    #pragma unroll
    for (int i0 = 0; i0 < 8; i0++) {
        int i = i0 * 512 + t;
        int r = i >> 5, kp = i & 31;
        int row = min(rowb + r, NN - 1);
        float2 vz = *(const float2*)(g_z + (size_t)row * DIM + kp * 2);
        float2 vx = *(const float2*)(x + (size_t)row * DIM + kp * 2);
        store_pair(sm + P_A(0), sm + P_AL(0), swz<7>((uint32_t)(r * 128 + kp * 4)),
                   make_float2(vz.x + vx.x, vz.y + vx.y));
    }

    float acc[2][8][4];
    #pragma unroll
    for (int mf = 0; mf < 2; mf++)
        #pragma unroll
        for (int nf = 0; nf < 8; nf++) {
            acc[mf][nf][0] = 0.f; acc[mf][nf][1] = 0.f;
            acc[mf][nf][2] = 0.f; acc[mf][nf][3] = 0.f;
        }

    #pragma unroll 1
    for (int c = 0; c < 4; c++) {
        cpa_wait0();
        __syncthreads();
        if (c < 3) {
            int nb = (c + 1) & 1;
            #pragma unroll
            for (int i0 = 0; i0 < 4; i0++) {
                int i = i0 * 512 + t;
                cpa16(sb + P_B(nb) + i * 16, g_w1H + (c + 1) * 32768 + i * 16);
                cpa16(sb + P_BL(nb) + i * 16, g_w1L + (c + 1) * 32768 + i * 16);
            }
            cpa_commit();
            #pragma unroll
            for (int i0 = 0; i0 < 8; i0++) {
                int i = i0 * 512 + t;
                int r = i >> 5, kp = i & 31;
                int row = min(rowb + r, NN - 1);
                float2 vz = *(const float2*)(g_z + (size_t)row * DIM + (c + 1) * 64 + kp * 2);
                float2 vx = *(const float2*)(x + (size_t)row * DIM + (c + 1) * 64 + kp * 2);
                store_pair(sm + P_A(nb), sm + P_AL(nb),
                           swz<7>((uint32_t)(r * 128 + kp * 4)),
                           make_float2(vz.x + vx.x, vz.y + vx.y));
            }
        }
        int cb = c & 1;
        mma_chunk(acc, sb + P_A(cb), sb + P_AL(cb), sb + P_B(cb), sb + P_BL(cb),
                  wm * 32, wn * 64, l);
    }

    // epilogue: relu(+b1) -> h1 images
    #pragma unroll
    for (int mf = 0; mf < 2; mf++)
        #pragma unroll
        for (int rh = 0; rh < 2; rh++) {
            int r = wm * 32 + mf * 16 + rh * 8 + (l >> 2);
            if (rowb + r < NN) {
                #pragma unroll
                for (int nq = 0; nq < 4; nq++) {
                    int col = wn * 64 + nq * 16 + 4 * j;
                    float4 bv = ((const float4*)b1)[col >> 2];
                    float h0 = fmaxf(acc[mf][2 * nq][2 * rh]     + bv.x, 0.f);
                    float h1 = fmaxf(acc[mf][2 * nq][2 * rh + 1] + bv.y, 0.f);
                    float h2 = fmaxf(acc[mf][2 * nq + 1][2 * rh]     + bv.z, 0.f);
                    float h3 = fmaxf(acc[mf][2 * nq + 1][2 * rh + 1] + bv.w, 0.f);
                    __nv_bfloat16 b0 = __float2bfloat16(h0), b1v = __float2bfloat16(h1);
                    __nv_bfloat16 b2 = __float2bfloat16(h2), b3 = __float2bfloat16(h3);
                    __nv_bfloat16 c0 = __float2bfloat16(h0 - __bfloat162float(b0));
                    __nv_bfloat16 c1 = __float2bfloat16(h1 - __bfloat162float(b1v));
                    __nv_bfloat16 c2 = __float2bfloat16(h2 - __bfloat162float(b2));
                    __nv_bfloat16 c3 = __float2bfloat16(h3 - __bfloat162float(b3));
                    int kc = col >> 6, kp = col & 63;
                    uint32_t off = (uint32_t)(rb * 65536 + kc * 16384)
                                 + swz<7>((uint32_t)(r * 128 + kp * 2));
                    __nv_bfloat162 hA = __halves2bfloat162(b0, b1v);
                    __nv_bfloat162 hB = __halves2bfloat162(b2, b3);
                    *(ull*)(g_h1H + off) =
                        ((ull)*(uint32_t*)&hB << 32) | *(uint32_t*)&hA;
                    __nv_bfloat162 lA = __halves2bfloat162(c0, c1);
                    __nv_bfloat162 lB = __halves2bfloat162(c2, c3);
                    *(ull*)(g_h1L + off) =
                        ((ull)*(uint32_t*)&lB << 32) | *(uint32_t*)&lA;
                }
            }
        }
}

// Kernel 4: h = relu(h1 @ W2 + b2) + x -> g_z (pre-LN)
__global__ __launch_bounds__(512, 1) void k_mlp2(const float* __restrict__ x,
                                                 const float* __restrict__ b2)
{
    extern __shared__ char sm[];
    const int t = threadIdx.x, w = t >> 5, l = t & 31;
    const int wm = w & 3, wn = w >> 2, j = l & 3;
    const uint32_t sb = smem_u32(sm);
    const int rb = blockIdx.x, rowb = rb * 128;

    // prologue: B0 + A0 all cp.async
    #pragma unroll
    for (int i0 = 0; i0 < 4; i0++) {
        int i = i0 * 512 + t;
        cpa16(sb + P_B(0) + i * 16, g_w2H + i * 16);
        cpa16(sb + P_BL(0) + i * 16, g_w2L + i * 16);
    }
    #pragma unroll
    for (int i0 = 0; i0 < 2; i0++) {
        int i = i0 * 512 + t;
        cpa16(sb + P_A(0) + i * 16, g_h1H + (size_t)rb * 65536 + i * 16);
        cpa16(sb + P_AL(0) + i * 16, g_h1L + (size_t)rb * 65536 + i * 16);
    }
    cpa_commit();

    float acc[2][8][4];
    #pragma unroll
    for (int mf = 0; mf < 2; mf++)
        #pragma unroll
        for (int nf = 0; nf < 8; nf++) {
            acc[mf][nf][0] = 0.f; acc[mf][nf][1] = 0.f;
            acc[mf][nf][2] = 0.f; acc[mf][nf][3] = 0.f;
        }

    #pragma unroll 1
    for (int c = 0; c < 4; c++) {
        cpa_wait0();
        __syncthreads();
        if (c < 3) {
            int nb = (c + 1) & 1;
            #pragma unroll
            for (int i0 = 0; i0 < 4; i0++) {
                int i = i0 * 512 + t;
                cpa16(sb + P_B(nb) + i * 16, g_w2H + (c + 1) * 32768 + i * 16);
                cpa16(sb + P_BL(nb) + i * 16, g_w2L + (c + 1) * 32768 + i * 16);
            }
            #pragma unroll
            for (int i0 = 0; i0 < 2; i0++) {
                int i = i0 * 512 + t;
                cpa16(sb + P_A(nb) + i * 16,
                      g_h1H + (size_t)rb * 65536 + (c + 1) * 16384 + i * 16);
                cpa16(sb + P_AL(nb) + i * 16,
                      g_h1L + (size_t)rb * 65536 + (c + 1) * 16384 + i * 16);
            }
            cpa_commit();
        }
        int cb = c & 1;
        mma_chunk(acc, sb + P_A(cb), sb + P_AL(cb), sb + P_B(cb), sb + P_BL(cb),
                  wm * 32, wn * 64, l);
    }

    // epilogue: relu(+b2) + x -> g_z
    #pragma unroll
    for (int mf = 0; mf < 2; mf++)
        #pragma unroll
        for (int rh = 0; rh < 2; rh++) {
            int r = wm * 32 + mf * 16 + rh * 8 + (l >> 2);
            int grow = rowb + r;
            if (grow < NN) {
                #pragma unroll
                for (int nq = 0; nq < 4; nq++) {
                    int col = wn * 64 + nq * 16 + 4 * j;
                    float4 bv = ((const float4*)b2)[col >> 2];
                    float4 xv = ((const float4*)(x + (size_t)grow * DIM))[col >> 2];
                    float4 o;
                    o.x = fmaxf(acc[mf][2 * nq][2 * rh]     + bv.x, 0.f) + xv.x;
                    o.y = fmaxf(acc[mf][2 * nq][2 * rh + 1] + bv.y, 0.f) + xv.y;
                    o.z = fmaxf(acc[mf][2 * nq + 1][2 * rh]     + bv.z, 0.f) + xv.z;
                    o.w = fmaxf(acc[mf][2 * nq + 1][2 * rh + 1] + bv.w, 0.f) + xv.w;
                    ((float4*)(g_z + (size_t)grow * DIM))[col >> 2] = o;
                }
            }
        }
}

// Kernel 5: out = LayerNorm(g_z) * gamma + beta; then zero g_z for next replay
__global__ __launch_bounds__(256) void k_ln(const float* __restrict__ gamma,
                                            const float* __restrict__ beta,
                                            float* __restrict__ out)
{
    const int w = threadIdx.x >> 5, l = threadIdx.x & 31;
    const int row = blockIdx.x * 8 + w;
    float4* hr = (float4*)(g_z + (size_t)row * DIM);
    float4 v0 = hr[l], v1 = hr[32 + l];
    float s = v0.x + v0.y + v0.z + v0.w + v1.x + v1.y + v1.z + v1.w;
    float q = v0.x * v0.x + v0.y * v0.y + v0.z * v0.z + v0.w * v0.w
            + v1.x * v1.x + v1.y * v1.y + v1.z * v1.z + v1.w * v1.w;
    #pragma unroll
    for (int o = 16; o; o >>= 1) {
        s += __shfl_xor_sync(0xffffffffu, s, o);
        q += __shfl_xor_sync(0xffffffffu, q, o);
    }
    float mu = s * (1.0f / 256.0f);
    float var = q * (1.0f / 256.0f) - mu * mu;
    float inv = rsqrtf(var + 1e-5f);
    float4 ga = ((const float4*)gamma)[l], gb = ((const float4*)gamma)[32 + l];
    float4 ba = ((const float4*)beta)[l],  bb = ((const float4*)beta)[32 + l];
    float4 o0, o1;
    o0.x = (v0.x - mu) * inv * ga.x + ba.x;
    o0.y = (v0.y - mu) * inv * ga.y + ba.y;
    o0.z = (v0.z - mu) * inv * ga.z + ba.z;
    o0.w = (v0.w - mu) * inv * ga.w + ba.w;
    o1.x = (v1.x - mu) * inv * gb.x + bb.x;
    o1.y = (v1.y - mu) * inv * gb.y + bb.y;
    o1.z = (v1.z - mu) * inv * gb.z + bb.z;
    o1.w = (v1.w - mu) * inv * gb.w + bb.w;
    ((float4*)(out + (size_t)row * DIM))[l] = o0;
    ((float4*)(out + (size_t)row * DIM))[32 + l] = o1;
    // restore g_z = 0 so next graph replay's atomics start clean
    float4 zz = make_float4(0.f, 0.f, 0.f, 0.f);
    hr[l] = zz;
    hr[32 + l] = zz;
}

// ---------------------------------------------------------------------------
extern "C" void kernel_launch(void* const* d_in, const int* in_sizes, int n_in,
                              void* d_out, int out_size)
{
    const float* x     = (const float*)d_in[0];
    const int*   eidx  = (const int*)d_in[1];     // int32 (JAX x64 disabled)
    const float* ea    = (const float*)d_in[2];
    const float* We    = (const float*)d_in[3];
    const float* be    = (const float*)d_in[4];
    const float* W1    = (const float*)d_in[5];
    const float* b1    = (const float*)d_in[6];
    const float* W2    = (const float*)d_in[7];
    const float* b2    = (const float*)d_in[8];
    const float* gamma = (const float*)d_in[9];
    const float* beta  = (const float*)d_in[10];
    float* out         = (float*)d_out;

    cudaFuncSetAttribute(k_edge, cudaFuncAttributeMaxDynamicSharedMemorySize, E_SMEM);
    cudaFuncSetAttribute(k_mlp1, cudaFuncAttributeMaxDynamicSharedMemorySize, P_SMEM);
    cudaFuncSetAttribute(k_mlp2, cudaFuncAttributeMaxDynamicSharedMemorySize, P_SMEM);

    k_prep<<<288, 256>>>(We, W1, W2);
    k_edge<<<6250, 512, E_SMEM>>>(x, eidx, ea, be);
    k_mlp1<<<RB, 512, P_SMEM>>>(x, b1);
    k_mlp2<<<RB, 512, P_SMEM>>>(x, b2);
    k_ln<<<6250, 256>>>(gamma, beta, out);
}

// round 9
// speedup vs baseline: 1.3247x; 1.3247x over previous
#include <cuda_runtime.h>
#include <cuda_bf16.h>
#include <cstdint>

#define NN 50000
#define NE 800000
#define DIM 256
#define RB 391   // ceil(NN/128)

typedef unsigned long long ull;

// ---------------- global scratch ----------------
__device__ __align__(16) float g_z[NN * DIM];          // z = x + aggr; later pre-LN h
__device__ __align__(128) char g_weH[32768];           // We image  [64k][256n] bf16 hi
__device__ __align__(128) char g_weL[32768];
__device__ __align__(128) char g_w1H[131072];          // W1 images, 4 chunks x 32KB
__device__ __align__(128) char g_w1L[131072];
__device__ __align__(128) char g_w2H[131072];
__device__ __align__(128) char g_w2L[131072];
__device__ __align__(128) char g_h1H[RB * 65536];      // h1 A-images (per rowblock, 4 kc x 16KB)
__device__ __align__(128) char g_h1L[RB * 65536];

// ---------------- helpers ----------------
template <int S>
__device__ __forceinline__ uint32_t swz(uint32_t off) {
    return off ^ (((off >> S) & 7u) << 4);
}
// column-pair permutation so MMA C-fragments give 4 consecutive logical cols
__device__ __forceinline__ int permp(int np) {
    return (np & ~7) | ((np & 7) >> 1) | ((np & 1) << 2);
}
__device__ __forceinline__ uint32_t smem_u32(const void* p) {
    uint32_t a;
    asm("{ .reg .u64 t; cvta.to.shared.u64 t, %1; cvt.u32.u64 %0, t; }" : "=r"(a) : "l"(p));
    return a;
}
__device__ __forceinline__ void ldsm4(uint32_t r[4], uint32_t a) {
    asm volatile("ldmatrix.sync.aligned.m8n8.x4.shared.b16 {%0,%1,%2,%3}, [%4];"
                 : "=r"(r[0]), "=r"(r[1]), "=r"(r[2]), "=r"(r[3]) : "r"(a));
}
__device__ __forceinline__ void ldsm4t(uint32_t r[4], uint32_t a) {
    asm volatile("ldmatrix.sync.aligned.m8n8.x4.trans.shared.b16 {%0,%1,%2,%3}, [%4];"
                 : "=r"(r[0]), "=r"(r[1]), "=r"(r[2]), "=r"(r[3]) : "r"(a));
}
__device__ __forceinline__ void mma16816(float d[4], const uint32_t a[4], const uint32_t b[2]) {
    asm volatile("mma.sync.aligned.m16n8k16.row.col.f32.bf16.bf16.f32 "
                 "{%0,%1,%2,%3}, {%4,%5,%6,%7}, {%8,%9}, {%0,%1,%2,%3};"
                 : "+f"(d[0]), "+f"(d[1]), "+f"(d[2]), "+f"(d[3])
                 : "r"(a[0]), "r"(a[1]), "r"(a[2]), "r"(a[3]), "r"(b[0]), "r"(b[1]));
}
__device__ __forceinline__ void red4(float* a, float4 v) {
    asm volatile("red.global.add.v4.f32 [%0], {%1,%2,%3,%4};"
                 :: "l"(a), "f"(v.x), "f"(v.y), "f"(v.z), "f"(v.w));
}
__device__ __forceinline__ void cpa16(uint32_t dst, const void* src) {
    asm volatile("cp.async.cg.shared.global [%0], [%1], 16;" :: "r"(dst), "l"(src));
}
__device__ __forceinline__ void cpa_commit() { asm volatile("cp.async.commit_group;"); }
__device__ __forceinline__ void cpa_wait0()  { asm volatile("cp.async.wait_group 0;"); }

__device__ __forceinline__ void store_pair(char* bH, char* bL, uint32_t off, float2 v) {
    __nv_bfloat16 h0 = __float2bfloat16(v.x), h1 = __float2bfloat16(v.y);
    __nv_bfloat16 l0 = __float2bfloat16(v.x - __bfloat162float(h0));
    __nv_bfloat16 l1 = __float2bfloat16(v.y - __bfloat162float(h1));
    *(__nv_bfloat162*)(bH + off) = __halves2bfloat162(h0, h1);
    *(__nv_bfloat162*)(bL + off) = __halves2bfloat162(l0, l1);
}

// ---------------------------------------------------------------------------
// Mainloop chunk: acc += A[32 rows x 64k] @ B[64k x 64 cols] with 3-pass bf16
// split (Ah*Bh + Ah*Bl + Al*Bh). A: 128B rows swz<7>; B: 512B rows swz<9>.
// ---------------------------------------------------------------------------
__device__ __forceinline__ void mma_chunk(float acc[2][8][4],
    uint32_t aH, uint32_t aL, uint32_t bH, uint32_t bL,
    int mbase, int nbase, int l)
{
    const int lr = l & 7, lg8 = ((l >> 3) & 1) * 8, lh8 = (l >> 4) * 8;
    #pragma unroll
    for (int ks = 0; ks < 4; ks++) {
        uint32_t a[2][4], bh[8][2], bl[8][2];
        #pragma unroll
        for (int mf = 0; mf < 2; mf++)
            ldsm4(a[mf], aH + swz<7>((uint32_t)((mbase + mf * 16 + lr + lg8) * 128
                                                + (ks * 16 + lh8) * 2)));
        #pragma unroll
        for (int nq = 0; nq < 4; nq++) {
            uint32_t r4[4];
            uint32_t off = swz<9>((uint32_t)((ks * 16 + lr + lg8) * 512
                                             + (nbase + nq * 16 + lh8) * 2));
            ldsm4t(r4, bH + off);
            bh[2 * nq][0] = r4[0]; bh[2 * nq][1] = r4[1];
            bh[2 * nq + 1][0] = r4[2]; bh[2 * nq + 1][1] = r4[3];
            ldsm4t(r4, bL + off);
            bl[2 * nq][0] = r4[0]; bl[2 * nq][1] = r4[1];
            bl[2 * nq + 1][0] = r4[2]; bl[2 * nq + 1][1] = r4[3];
        }
        #pragma unroll
        for (int mf = 0; mf < 2; mf++)
            #pragma unroll
            for (int nf = 0; nf < 8; nf++)
                mma16816(acc[mf][nf], a[mf], bh[nf]);
        #pragma unroll
        for (int mf = 0; mf < 2; mf++)
            #pragma unroll
            for (int nf = 0; nf < 8; nf++)
                mma16816(acc[mf][nf], a[mf], bl[nf]);
        #pragma unroll
        for (int mf = 0; mf < 2; mf++)
            ldsm4(a[mf], aL + swz<7>((uint32_t)((mbase + mf * 16 + lr + lg8) * 128
                                                + (ks * 16 + lh8) * 2)));
        #pragma unroll
        for (int mf = 0; mf < 2; mf++)
            #pragma unroll
            for (int nf = 0; nf < 8; nf++)
                mma16816(acc[mf][nf], a[mf], bh[nf]);
    }
}

// ---------------------------------------------------------------------------
// k_prep: build bf16 hi/lo weight images (smem byte layout, swizzle+perm baked)
// ---------------------------------------------------------------------------
__global__ __launch_bounds__(256) void k_prep(const float* __restrict__ We,
                                              const float* __restrict__ W1,
                                              const float* __restrict__ W2)
{
    int i = blockIdx.x * 256 + threadIdx.x;
    if (i < 8192) {                       // We: 64k x 128 pairs
        int k = i >> 7, np = i & 127;
        uint32_t off = swz<9>((uint32_t)(k * 512 + permp(np) * 4));
        store_pair(g_weH, g_weL, off, ((const float2*)We)[i]);
    } else if (i < 40960) {               // W1: 4 chunks x 64k x 128 pairs
        int j = i - 8192;
        int kc = j >> 13, k = (j >> 7) & 63, np = j & 127;
        uint32_t off = (uint32_t)(kc * 32768) + swz<9>((uint32_t)(k * 512 + permp(np) * 4));
        store_pair(g_w1H, g_w1L, off, ((const float2*)W1)[j]);
    } else if (i < 73728) {               // W2
        int j = i - 40960;
        int kc = j >> 13, k = (j >> 7) & 63, np = j & 127;
        uint32_t off = (uint32_t)(kc * 32768) + swz<9>((uint32_t)(k * 512 + permp(np) * 4));
        store_pair(g_w2H, g_w2L, off, ((const float2*)W2)[j]);
    }
}

// ---------------------------------------------------------------------------
// k_init: z = x
// ---------------------------------------------------------------------------
__global__ __launch_bounds__(256) void k_init(const float4* __restrict__ x) {
    int i = blockIdx.x * 256 + threadIdx.x;
    reinterpret_cast<float4*>(g_z)[i] = x[i];
}

// ---------------------------------------------------------------------------
// k_edge: CTA = 128 edges, 256 threads (wm4 x wn2), N in 2 halves, occ 2.
// msg = relu(ea@We + x[src] + be) -> red.v4 into g_z[dst].
// x[src] gathers are register-pipelined: edge0 prefetched under the MMA,
// edge q+1 prefetched while edge q's atomics issue.
// ---------------------------------------------------------------------------
#define E_AH 0
#define E_AL 16384
#define E_BH 32768
#define E_BL 65536
#define E_SMEM 98304

__global__ __launch_bounds__(256, 2) void k_edge(
    const float* __restrict__ x, const int* __restrict__ eidx,
    const float* __restrict__ ea, const float* __restrict__ be)
{
    extern __shared__ char sm[];
    const int t = threadIdx.x, w = t >> 5, l = t & 31;
    const int wm = w & 3, wn = w >> 2, j = l & 3;
    const uint32_t sb = smem_u32(sm);

    // B: bulk cp.async of pre-built We images
    #pragma unroll
    for (int i0 = 0; i0 < 8; i0++) {
        int i = i0 * 256 + t;
        cpa16(sb + E_BH + i * 16, g_weH + i * 16);
        cpa16(sb + E_BL + i * 16, g_weL + i * 16);
    }
    cpa_commit();

    // A: convert edge_attr tile [128][64] to bf16 hi/lo
    const float2* ea2 = (const float2*)(ea + (size_t)blockIdx.x * (128 * 64));
    #pragma unroll
    for (int i0 = 0; i0 < 16; i0++) {
        int i = i0 * 256 + t;
        int r = i >> 5, kp = i & 31;
        store_pair(sm + E_AH, sm + E_AL, swz<7>((uint32_t)(r * 128 + kp * 4)), ea2[i]);
    }
    cpa_wait0();
    __syncthreads();

    // per-thread edge rows (4): wm*32 + mf*16 + rh*8 + (l>>2);  q = mf*2+rh
    int si[4], di[4];
    #pragma unroll
    for (int q = 0; q < 4; q++) {
        int r = wm * 32 + (q >> 1) * 16 + (q & 1) * 8 + (l >> 2);
        long long e = (long long)blockIdx.x * 128 + r;
        si[q] = eidx[e]; di[q] = eidx[NE + e];
    }

    #pragma unroll 1
    for (int hf = 0; hf < 2; hf++) {
        const int colbase = hf * 128 + wn * 64;
        // prefetch edge 0's x-chunks + be for this half (hidden under the MMA)
        float4 xv[4], bv[4];
        #pragma unroll
        for (int nq = 0; nq < 4; nq++) {
            int c4 = (colbase + nq * 16 + 4 * j) >> 2;
            xv[nq] = __ldg((const float4*)(x + (size_t)si[0] * DIM) + c4);
            bv[nq] = __ldg((const float4*)be + c4);
        }

        float acc[2][8][4];
        #pragma unroll
        for (int mf = 0; mf < 2; mf++)
            #pragma unroll
            for (int nf = 0; nf < 8; nf++) {
                acc[mf][nf][0] = 0.f; acc[mf][nf][1] = 0.f;
                acc[mf][nf][2] = 0.f; acc[mf][nf][3] = 0.f;
            }
        mma_chunk(acc, sb + E_AH, sb + E_AL, sb + E_BH, sb + E_BL,
                  wm * 32, colbase, l);

        // pipelined epilogue over the 4 edges
        #pragma unroll
        for (int q = 0; q < 4; q++) {
            float4 cur[4];
            #pragma unroll
            for (int nq = 0; nq < 4; nq++) cur[nq] = xv[nq];
            if (q < 3) {
                #pragma unroll
                for (int nq = 0; nq < 4; nq++) {
                    int c4 = (colbase + nq * 16 + 4 * j) >> 2;
                    xv[nq] = __ldg((const float4*)(x + (size_t)si[q + 1] * DIM) + c4);
                }
            }
            const int mf = q >> 1, rh = q & 1;
            float* zd = g_z + (size_t)di[q] * DIM;
            #pragma unroll
            for (int nq = 0; nq < 4; nq++) {
                int col = colbase + nq * 16 + 4 * j;
                float4 o;
                o.x = fmaxf(acc[mf][2 * nq][2 * rh]     + cur[nq].x + bv[nq].x, 0.f);
                o.y = fmaxf(acc[mf][2 * nq][2 * rh + 1] + cur[nq].y + bv[nq].y, 0.f);
                o.z = fmaxf(acc[mf][2 * nq + 1][2 * rh]     + cur[nq].z + bv[nq].z, 0.f);
                o.w = fmaxf(acc[mf][2 * nq + 1][2 * rh + 1] + cur[nq].w + bv[nq].w, 0.f);
                red4(zd + col, o);
            }
        }
    }
}

// ---------------------------------------------------------------------------
// MLP kernels: 512 threads (wm 4 x wn 4), CTA = 128 rows x 256 cols,
// K=256 in 4 chunks, double-buffered cp.async for B (and A in mlp2).
// ---------------------------------------------------------------------------
#define P_A(buf)  ((buf) * 32768)              // A hi at 0 / 32768
#define P_AL(buf) ((buf) * 32768 + 16384)
#define P_B(buf)  (65536 + (buf) * 65536)      // B hi at 65536 / 131072
#define P_BL(buf) (65536 + (buf) * 65536 + 32768)
#define P_SMEM 196608

// Kernel 3: h1 = relu(z @ W1 + b1) -> bf16 hi/lo A-images for mlp2
__global__ __launch_bounds__(512, 1) void k_mlp1(const float* __restrict__ b1)
{
    extern __shared__ char sm[];
    const int t = threadIdx.x, w = t >> 5, l = t & 31;
    const int wm = w & 3, wn = w >> 2, j = l & 3;
    const uint32_t sb = smem_u32(sm);
    const int rb = blockIdx.x, rowb = rb * 128;

    // prologue: B0 cp.async + A0 convert
    #pragma unroll
    for (int i0 = 0; i0 < 4; i0++) {
        int i = i0 * 512 + t;
        cpa16(sb + P_B(0) + i * 16, g_w1H + i * 16);
        cpa16(sb + P_BL(0) + i * 16, g_w1L + i * 16);
    }
    cpa_commit();
    #pragma unroll
    for (int i0 = 0; i0 < 8; i0++) {
        int i = i0 * 512 + t;
        int r = i >> 5, kp = i & 31;
        int row = min(rowb + r, NN - 1);
        float2 v = *(const float2*)(g_z + (size_t)row * DIM + kp * 2);
        store_pair(sm + P_A(0), sm + P_AL(0), swz<7>((uint32_t)(r * 128 + kp * 4)), v);
    }

    float acc[2][8][4];
    #pragma unroll
    for (int mf = 0; mf < 2; mf++)
        #pragma unroll
        for (int nf = 0; nf < 8; nf++) {
            acc[mf][nf][0] = 0.f; acc[mf][nf][1] = 0.f;
            acc[mf][nf][2] = 0.f; acc[mf][nf][3] = 0.f;
        }

    #pragma unroll 1
    for (int c = 0; c < 4; c++) {
        cpa_wait0();
        __syncthreads();
        if (c < 3) {
            int nb = (c + 1) & 1;
            #pragma unroll
            for (int i0 = 0; i0 < 4; i0++) {
                int i = i0 * 512 + t;
                cpa16(sb + P_B(nb) + i * 16, g_w1H + (c + 1) * 32768 + i * 16);
                cpa16(sb + P_BL(nb) + i * 16, g_w1L + (c + 1) * 32768 + i * 16);
            }
            cpa_commit();
            #pragma unroll
            for (int i0 = 0; i0 < 8; i0++) {
                int i = i0 * 512 + t;
                int r = i >> 5, kp = i & 31;
                int row = min(rowb + r, NN - 1);
                float2 v = *(const float2*)(g_z + (size_t)row * DIM + (c + 1) * 64 + kp * 2);
                store_pair(sm + P_A(nb), sm + P_AL(nb),
                           swz<7>((uint32_t)(r * 128 + kp * 4)), v);
            }
        }
        int cb = c & 1;
        mma_chunk(acc, sb + P_A(cb), sb + P_AL(cb), sb + P_B(cb), sb + P_BL(cb),
                  wm * 32, wn * 64, l);
    }

    // epilogue: relu(+b1) -> h1 images
    #pragma unroll
    for (int mf = 0; mf < 2; mf++)
        #pragma unroll
        for (int rh = 0; rh < 2; rh++) {
            int r = wm * 32 + mf * 16 + rh * 8 + (l >> 2);
            if (rowb + r < NN) {
                #pragma unroll
                for (int nq = 0; nq < 4; nq++) {
                    int col = wn * 64 + nq * 16 + 4 * j;
                    float4 bv = ((const float4*)b1)[col >> 2];
                    float h0 = fmaxf(acc[mf][2 * nq][2 * rh]     + bv.x, 0.f);
                    float h1 = fmaxf(acc[mf][2 * nq][2 * rh + 1] + bv.y, 0.f);
                    float h2 = fmaxf(acc[mf][2 * nq + 1][2 * rh]     + bv.z, 0.f);
                    float h3 = fmaxf(acc[mf][2 * nq + 1][2 * rh + 1] + bv.w, 0.f);
                    __nv_bfloat16 b0 = __float2bfloat16(h0), b1v = __float2bfloat16(h1);
                    __nv_bfloat16 b2 = __float2bfloat16(h2), b3 = __float2bfloat16(h3);
                    __nv_bfloat16 c0 = __float2bfloat16(h0 - __bfloat162float(b0));
                    __nv_bfloat16 c1 = __float2bfloat16(h1 - __bfloat162float(b1v));
                    __nv_bfloat16 c2 = __float2bfloat16(h2 - __bfloat162float(b2));
                    __nv_bfloat16 c3 = __float2bfloat16(h3 - __bfloat162float(b3));
                    int kc = col >> 6, kp = col & 63;
                    uint32_t off = (uint32_t)(rb * 65536 + kc * 16384)
                                 + swz<7>((uint32_t)(r * 128 + kp * 2));
                    __nv_bfloat162 hA = __halves2bfloat162(b0, b1v);
                    __nv_bfloat162 hB = __halves2bfloat162(b2, b3);
                    *(ull*)(g_h1H + off) =
                        ((ull)*(uint32_t*)&hB << 32) | *(uint32_t*)&hA;
                    __nv_bfloat162 lA = __halves2bfloat162(c0, c1);
                    __nv_bfloat162 lB = __halves2bfloat162(c2, c3);
                    *(ull*)(g_h1L + off) =
                        ((ull)*(uint32_t*)&lB << 32) | *(uint32_t*)&lA;
                }
            }
        }
}

// Kernel 4: h = relu(h1 @ W2 + b2) + x -> g_z (pre-LN)
__global__ __launch_bounds__(512, 1) void k_mlp2(const float* __restrict__ x,
                                                 const float* __restrict__ b2)
{
    extern __shared__ char sm[];
    const int t = threadIdx.x, w = t >> 5, l = t & 31;
    const int wm = w & 3, wn = w >> 2, j = l & 3;
    const uint32_t sb = smem_u32(sm);
    const int rb = blockIdx.x, rowb = rb * 128;

    // prologue: B0 + A0 all cp.async
    #pragma unroll
    for (int i0 = 0; i0 < 4; i0++) {
        int i = i0 * 512 + t;
        cpa16(sb + P_B(0) + i * 16, g_w2H + i * 16);
        cpa16(sb + P_BL(0) + i * 16, g_w2L + i * 16);
    }
    #pragma unroll
    for (int i0 = 0; i0 < 2; i0++) {
        int i = i0 * 512 + t;
        cpa16(sb + P_A(0) + i * 16, g_h1H + (size_t)rb * 65536 + i * 16);
        cpa16(sb + P_AL(0) + i * 16, g_h1L + (size_t)rb * 65536 + i * 16);
    }
    cpa_commit();

    float acc[2][8][4];
    #pragma unroll
    for (int mf = 0; mf < 2; mf++)
        #pragma unroll
        for (int nf = 0; nf < 8; nf++) {
            acc[mf][nf][0] = 0.f; acc[mf][nf][1] = 0.f;
            acc[mf][nf][2] = 0.f; acc[mf][nf][3] = 0.f;
        }

    #pragma unroll 1
    for (int c = 0; c < 4; c++) {
        cpa_wait0();
        __syncthreads();
        if (c < 3) {
            int nb = (c + 1) & 1;
            #pragma unroll
            for (int i0 = 0; i0 < 4; i0++) {
                int i = i0 * 512 + t;
                cpa16(sb + P_B(nb) + i * 16, g_w2H + (c + 1) * 32768 + i * 16);
                cpa16(sb + P_BL(nb) + i * 16, g_w2L + (c + 1) * 32768 + i * 16);
            }
            #pragma unroll
            for (int i0 = 0; i0 < 2; i0++) {
                int i = i0 * 512 + t;
                cpa16(sb + P_A(nb) + i * 16,
                      g_h1H + (size_t)rb * 65536 + (c + 1) * 16384 + i * 16);
                cpa16(sb + P_AL(nb) + i * 16,
                      g_h1L + (size_t)rb * 65536 + (c + 1) * 16384 + i * 16);
            }
            cpa_commit();
        }
        int cb = c & 1;
        mma_chunk(acc, sb + P_A(cb), sb + P_AL(cb), sb + P_B(cb), sb + P_BL(cb),
                  wm * 32, wn * 64, l);
    }

    // epilogue: relu(+b2) + x -> g_z
    #pragma unroll
    for (int mf = 0; mf < 2; mf++)
        #pragma unroll
        for (int rh = 0; rh < 2; rh++) {
            int r = wm * 32 + mf * 16 + rh * 8 + (l >> 2);
            int grow = rowb + r;
            if (grow < NN) {
                #pragma unroll
                for (int nq = 0; nq < 4; nq++) {
                    int col = wn * 64 + nq * 16 + 4 * j;
                    float4 bv = ((const float4*)b2)[col >> 2];
                    float4 xv = ((const float4*)(x + (size_t)grow * DIM))[col >> 2];
                    float4 o;
                    o.x = fmaxf(acc[mf][2 * nq][2 * rh]     + bv.x, 0.f) + xv.x;
                    o.y = fmaxf(acc[mf][2 * nq][2 * rh + 1] + bv.y, 0.f) + xv.y;
                    o.z = fmaxf(acc[mf][2 * nq + 1][2 * rh]     + bv.z, 0.f) + xv.z;
                    o.w = fmaxf(acc[mf][2 * nq + 1][2 * rh + 1] + bv.w, 0.f) + xv.w;
                    ((float4*)(g_z + (size_t)grow * DIM))[col >> 2] = o;
                }
            }
        }
}

// Kernel 5: out = LayerNorm(g_z) * gamma + beta    (warp per row)
__global__ __launch_bounds__(256) void k_ln(const float* __restrict__ gamma,
                                            const float* __restrict__ beta,
                                            float* __restrict__ out)
{
    const int w = threadIdx.x >> 5, l = threadIdx.x & 31;
    const int row = blockIdx.x * 8 + w;
    const float4* hr = (const float4*)(g_z + (size_t)row * DIM);
    float4 v0 = hr[l], v1 = hr[32 + l];
    float s = v0.x + v0.y + v0.z + v0.w + v1.x + v1.y + v1.z + v1.w;
    float q = v0.x * v0.x + v0.y * v0.y + v0.z * v0.z + v0.w * v0.w
            + v1.x * v1.x + v1.y * v1.y + v1.z * v1.z + v1.w * v1.w;
    #pragma unroll
    for (int o = 16; o; o >>= 1) {
        s += __shfl_xor_sync(0xffffffffu, s, o);
        q += __shfl_xor_sync(0xffffffffu, q, o);
    }
    float mu = s * (1.0f / 256.0f);
    float var = q * (1.0f / 256.0f) - mu * mu;
    float inv = rsqrtf(var + 1e-5f);
    float4 ga = ((const float4*)gamma)[l], gb = ((const float4*)gamma)[32 + l];
    float4 ba = ((const float4*)beta)[l],  bb = ((const float4*)beta)[32 + l];
    float4 o0, o1;
    o0.x = (v0.x - mu) * inv * ga.x + ba.x;
    o0.y = (v0.y - mu) * inv * ga.y + ba.y;
    o0.z = (v0.z - mu) * inv * ga.z + ba.z;
    o0.w = (v0.w - mu) * inv * ga.w + ba.w;
    o1.x = (v1.x - mu) * inv * gb.x + bb.x;
    o1.y = (v1.y - mu) * inv * gb.y + bb.y;
    o1.z = (v1.z - mu) * inv * gb.z + bb.z;
    o1.w = (v1.w - mu) * inv * gb.w + bb.w;
    ((float4*)(out + (size_t)row * DIM))[l] = o0;
    ((float4*)(out + (size_t)row * DIM))[32 + l] = o1;
}

// ---------------------------------------------------------------------------
extern "C" void kernel_launch(void* const* d_in, const int* in_sizes, int n_in,
                              void* d_out, int out_size)
{
    const float* x     = (const float*)d_in[0];
    const int*   eidx  = (const int*)d_in[1];     // int32 (JAX x64 disabled)
    const float* ea    = (const float*)d_in[2];
    const float* We    = (const float*)d_in[3];
    const float* be    = (const float*)d_in[4];
    const float* W1    = (const float*)d_in[5];
    const float* b1    = (const float*)d_in[6];
    const float* W2    = (const float*)d_in[7];
    const float* b2    = (const float*)d_in[8];
    const float* gamma = (const float*)d_in[9];
    const float* beta  = (const float*)d_in[10];
    float* out         = (float*)d_out;

    cudaFuncSetAttribute(k_edge, cudaFuncAttributeMaxDynamicSharedMemorySize, E_SMEM);
    cudaFuncSetAttribute(k_mlp1, cudaFuncAttributeMaxDynamicSharedMemorySize, P_SMEM);
    cudaFuncSetAttribute(k_mlp2, cudaFuncAttributeMaxDynamicSharedMemorySize, P_SMEM);

    k_prep<<<288, 256>>>(We, W1, W2);
    k_init<<<12500, 256>>>((const float4*)x);
    k_edge<<<6250, 256, E_SMEM>>>(x, eidx, ea, be);
    k_mlp1<<<RB, 512, P_SMEM>>>(b1);
    k_mlp2<<<RB, 512, P_SMEM>>>(x, b2);
    k_ln<<<6250, 256>>>(gamma, beta, out);
}

// round 11
// speedup vs baseline: 1.3746x; 1.0377x over previous
#include <cuda_runtime.h>
#include <cuda_bf16.h>
#include <cstdint>

#define NN 50000
#define NE 800000
#define DIM 256
#define RB 391   // ceil(NN/128)

typedef unsigned long long ull;

// ---------------- global scratch ----------------
__device__ __align__(16) float g_z[NN * DIM];          // z = x + aggr (k_init + edge atomics)
__device__ __align__(128) char g_weH[32768];           // We image  [64k][256n] bf16 hi
__device__ __align__(128) char g_weL[32768];
__device__ __align__(128) char g_w1H[131072];          // W1 images, 4 chunks x 32KB
__device__ __align__(128) char g_w1L[131072];
__device__ __align__(128) char g_w2H[131072];
__device__ __align__(128) char g_w2L[131072];

// ---------------- helpers ----------------
template <int S>
__device__ __forceinline__ uint32_t swz(uint32_t off) {
    return off ^ (((off >> S) & 7u) << 4);
}
// column-pair permutation so MMA C-fragments give 4 consecutive logical cols
__device__ __forceinline__ int permp(int np) {
    return (np & ~7) | ((np & 7) >> 1) | ((np & 1) << 2);
}
__device__ __forceinline__ uint32_t smem_u32(const void* p) {
    uint32_t a;
    asm("{ .reg .u64 t; cvta.to.shared.u64 t, %1; cvt.u32.u64 %0, t; }" : "=r"(a) : "l"(p));
    return a;
}
__device__ __forceinline__ void ldsm4(uint32_t r[4], uint32_t a) {
    asm volatile("ldmatrix.sync.aligned.m8n8.x4.shared.b16 {%0,%1,%2,%3}, [%4];"
                 : "=r"(r[0]), "=r"(r[1]), "=r"(r[2]), "=r"(r[3]) : "r"(a));
}
__device__ __forceinline__ void ldsm4t(uint32_t r[4], uint32_t a) {
    asm volatile("ldmatrix.sync.aligned.m8n8.x4.trans.shared.b16 {%0,%1,%2,%3}, [%4];"
                 : "=r"(r[0]), "=r"(r[1]), "=r"(r[2]), "=r"(r[3]) : "r"(a));
}
__device__ __forceinline__ void mma16816(float d[4], const uint32_t a[4], const uint32_t b[2]) {
    asm volatile("mma.sync.aligned.m16n8k16.row.col.f32.bf16.bf16.f32 "
                 "{%0,%1,%2,%3}, {%4,%5,%6,%7}, {%8,%9}, {%0,%1,%2,%3};"
                 : "+f"(d[0]), "+f"(d[1]), "+f"(d[2]), "+f"(d[3])
                 : "r"(a[0]), "r"(a[1]), "r"(a[2]), "r"(a[3]), "r"(b[0]), "r"(b[1]));
}
__device__ __forceinline__ void red4(float* a, float4 v) {
    asm volatile("red.global.add.v4.f32 [%0], {%1,%2,%3,%4};"
                 :: "l"(a), "f"(v.x), "f"(v.y), "f"(v.z), "f"(v.w));
}
__device__ __forceinline__ void cpa16(uint32_t dst, const void* src) {
    asm volatile("cp.async.cg.shared.global [%0], [%1], 16;" :: "r"(dst), "l"(src));
}
__device__ __forceinline__ void cpa_commit() { asm volatile("cp.async.commit_group;"); }
__device__ __forceinline__ void cpa_wait0()  { asm volatile("cp.async.wait_group 0;"); }

__device__ __forceinline__ void store_pair(char* bH, char* bL, uint32_t off, float2 v) {
    __nv_bfloat16 h0 = __float2bfloat16(v.x), h1 = __float2bfloat16(v.y);
    __nv_bfloat16 l0 = __float2bfloat16(v.x - __bfloat162float(h0));
    __nv_bfloat16 l1 = __float2bfloat16(v.y - __bfloat162float(h1));
    *(__nv_bfloat162*)(bH + off) = __halves2bfloat162(h0, h1);
    *(__nv_bfloat162*)(bL + off) = __halves2bfloat162(l0, l1);
}

// ---------------------------------------------------------------------------
// Mainloop chunk: acc += A[32 rows x 64k] @ B[64k x 64 cols] with 3-pass bf16
// split (Ah*Bh + Ah*Bl + Al*Bh). A: 128B rows swz<7>; B: 512B rows swz<9>.
// ---------------------------------------------------------------------------
__device__ __forceinline__ void mma_chunk(float acc[2][8][4],
    uint32_t aH, uint32_t aL, uint32_t bH, uint32_t bL,
    int mbase, int nbase, int l)
{
    const int lr = l & 7, lg8 = ((l >> 3) & 1) * 8, lh8 = (l >> 4) * 8;
    #pragma unroll
    for (int ks = 0; ks < 4; ks++) {
        uint32_t a[2][4], bh[8][2], bl[8][2];
        #pragma unroll
        for (int mf = 0; mf < 2; mf++)
            ldsm4(a[mf], aH + swz<7>((uint32_t)((mbase + mf * 16 + lr + lg8) * 128
                                                + (ks * 16 + lh8) * 2)));
        #pragma unroll
        for (int nq = 0; nq < 4; nq++) {
            uint32_t r4[4];
            uint32_t off = swz<9>((uint32_t)((ks * 16 + lr + lg8) * 512
                                             + (nbase + nq * 16 + lh8) * 2));
            ldsm4t(r4, bH + off);
            bh[2 * nq][0] = r4[0]; bh[2 * nq][1] = r4[1];
            bh[2 * nq + 1][0] = r4[2]; bh[2 * nq + 1][1] = r4[3];
            ldsm4t(r4, bL + off);
            bl[2 * nq][0] = r4[0]; bl[2 * nq][1] = r4[1];
            bl[2 * nq + 1][0] = r4[2]; bl[2 * nq + 1][1] = r4[3];
        }
        #pragma unroll
        for (int mf = 0; mf < 2; mf++)
            #pragma unroll
            for (int nf = 0; nf < 8; nf++)
                mma16816(acc[mf][nf], a[mf], bh[nf]);
        #pragma unroll
        for (int mf = 0; mf < 2; mf++)
            #pragma unroll
            for (int nf = 0; nf < 8; nf++)
                mma16816(acc[mf][nf], a[mf], bl[nf]);
        #pragma unroll
        for (int mf = 0; mf < 2; mf++)
            ldsm4(a[mf], aL + swz<7>((uint32_t)((mbase + mf * 16 + lr + lg8) * 128
                                                + (ks * 16 + lh8) * 2)));
        #pragma unroll
        for (int mf = 0; mf < 2; mf++)
            #pragma unroll
            for (int nf = 0; nf < 8; nf++)
                mma16816(acc[mf][nf], a[mf], bh[nf]);
    }
}

// ---------------------------------------------------------------------------
// k_prep: build bf16 hi/lo weight images (smem byte layout, swizzle+perm baked)
// ---------------------------------------------------------------------------
__global__ __launch_bounds__(256) void k_prep(const float* __restrict__ We,
                                              const float* __restrict__ W1,
                                              const float* __restrict__ W2)
{
    int i = blockIdx.x * 256 + threadIdx.x;
    if (i < 8192) {                       // We: 64k x 128 pairs
        int k = i >> 7, np = i & 127;
        uint32_t off = swz<9>((uint32_t)(k * 512 + permp(np) * 4));
        store_pair(g_weH, g_weL, off, ((const float2*)We)[i]);
    } else if (i < 40960) {               // W1: 4 chunks x 64k x 128 pairs
        int j = i - 8192;
        int kc = j >> 13, k = (j >> 7) & 63, np = j & 127;
        uint32_t off = (uint32_t)(kc * 32768) + swz<9>((uint32_t)(k * 512 + permp(np) * 4));
        store_pair(g_w1H, g_w1L, off, ((const float2*)W1)[j]);
    } else if (i < 73728) {               // W2
        int j = i - 40960;
        int kc = j >> 13, k = (j >> 7) & 63, np = j & 127;
        uint32_t off = (uint32_t)(kc * 32768) + swz<9>((uint32_t)(k * 512 + permp(np) * 4));
        store_pair(g_w2H, g_w2L, off, ((const float2*)W2)[j]);
    }
}

// ---------------------------------------------------------------------------
// k_init: z = x
// ---------------------------------------------------------------------------
__global__ __launch_bounds__(256) void k_init(const float4* __restrict__ x) {
    int i = blockIdx.x * 256 + threadIdx.x;
    reinterpret_cast<float4*>(g_z)[i] = x[i];
}

// ---------------------------------------------------------------------------
// k_edge: CTA = 128 edges, 256 threads (wm4 x wn2), N in 2 halves, occ 2.
// msg = relu(ea@We + x[src] + be) -> red.v4 into g_z[dst].
// ---------------------------------------------------------------------------
#define E_AH 0
#define E_AL 16384
#define E_BH 32768
#define E_BL 65536
#define E_SMEM 98304

__global__ __launch_bounds__(256, 2) void k_edge(
    const float* __restrict__ x, const int* __restrict__ eidx,
    const float* __restrict__ ea, const float* __restrict__ be)
{
    extern __shared__ char sm[];
    const int t = threadIdx.x, w = t >> 5, l = t & 31;
    const int wm = w & 3, wn = w >> 2, j = l & 3;
    const uint32_t sb = smem_u32(sm);

    // B: bulk cp.async of pre-built We images
    #pragma unroll
    for (int i0 = 0; i0 < 8; i0++) {
        int i = i0 * 256 + t;
        cpa16(sb + E_BH + i * 16, g_weH + i * 16);
        cpa16(sb + E_BL + i * 16, g_weL + i * 16);
    }
    cpa_commit();

    // A: convert edge_attr tile [128][64] to bf16 hi/lo
    const float2* ea2 = (const float2*)(ea + (size_t)blockIdx.x * (128 * 64));
    #pragma unroll
    for (int i0 = 0; i0 < 16; i0++) {
        int i = i0 * 256 + t;
        int r = i >> 5, kp = i & 31;
        store_pair(sm + E_AH, sm + E_AL, swz<7>((uint32_t)(r * 128 + kp * 4)), ea2[i]);
    }
    cpa_wait0();
    __syncthreads();

    // per-thread edge rows (4): wm*32 + mf*16 + rh*8 + (l>>2);  q = mf*2+rh
    int si[4], di[4];
    #pragma unroll
    for (int q = 0; q < 4; q++) {
        int r = wm * 32 + (q >> 1) * 16 + (q & 1) * 8 + (l >> 2);
        long long e = (long long)blockIdx.x * 128 + r;
        si[q] = eidx[e]; di[q] = eidx[NE + e];
    }

    #pragma unroll 1
    for (int hf = 0; hf < 2; hf++) {
        const int colbase = hf * 128 + wn * 64;
        // prefetch edge 0's x-chunks + be for this half (hidden under the MMA)
        float4 xv[4], bv[4];
        #pragma unroll
        for (int nq = 0; nq < 4; nq++) {
            int c4 = (colbase + nq * 16 + 4 * j) >> 2;
            xv[nq] = __ldg((const float4*)(x + (size_t)si[0] * DIM) + c4);
            bv[nq] = __ldg((const float4*)be + c4);
        }

        float acc[2][8][4];
        #pragma unroll
        for (int mf = 0; mf < 2; mf++)
            #pragma unroll
            for (int nf = 0; nf < 8; nf++) {
                acc[mf][nf][0] = 0.f; acc[mf][nf][1] = 0.f;
                acc[mf][nf][2] = 0.f; acc[mf][nf][3] = 0.f;
            }
        mma_chunk(acc, sb + E_AH, sb + E_AL, sb + E_BH, sb + E_BL,
                  wm * 32, colbase, l);

        // pipelined epilogue over the 4 edges
        #pragma unroll
        for (int q = 0; q < 4; q++) {
            float4 cur[4];
            #pragma unroll
            for (int nq = 0; nq < 4; nq++) cur[nq] = xv[nq];
            if (q < 3) {
                #pragma unroll
                for (int nq = 0; nq < 4; nq++) {
                    int c4 = (colbase + nq * 16 + 4 * j) >> 2;
                    xv[nq] = __ldg((const float4*)(x + (size_t)si[q + 1] * DIM) + c4);
                }
            }
            const int mf = q >> 1, rh = q & 1;
            float* zd = g_z + (size_t)di[q] * DIM;
            #pragma unroll
            for (int nq = 0; nq < 4; nq++) {
                int col = colbase + nq * 16 + 4 * j;
                float4 o;
                o.x = fmaxf(acc[mf][2 * nq][2 * rh]     + cur[nq].x + bv[nq].x, 0.f);
                o.y = fmaxf(acc[mf][2 * nq][2 * rh + 1] + cur[nq].y + bv[nq].y, 0.f);
                o.z = fmaxf(acc[mf][2 * nq + 1][2 * rh]     + cur[nq].z + bv[nq].z, 0.f);
                o.w = fmaxf(acc[mf][2 * nq + 1][2 * rh + 1] + cur[nq].w + bv[nq].w, 0.f);
                red4(zd + col, o);
            }
        }
    }
}

// ---------------------------------------------------------------------------
// k_mlp (FUSED): layer1 -> h1 images in smem -> layer2 -> LayerNorm -> out
// 512 threads (wm4 x wn4), CTA = 128 rows x 256 cols.
// Smem: [0,64K)  phase1 A dbuf   -> phase2 h1 images kc0,kc1
//       [64K,128K) phase1 B buf0 -> phase2 h1 images kc2,kc3
//       [128K,192K) phase1 B buf1 -> phase2 W2 stage (single buf) -> LN partials
// ---------------------------------------------------------------------------
#define P_A(buf)  ((buf) * 32768)
#define P_AL(buf) ((buf) * 32768 + 16384)
#define P_B(buf)  (65536 + (buf) * 65536)
#define P_BL(buf) (65536 + (buf) * 65536 + 32768)
#define H1(kc)    ((kc) * 32768)            // hi; lo = +16384
#define W2HI      131072
#define W2LO      163840
#define LNPART    131072
#define P_SMEM    196608

__global__ __launch_bounds__(512, 1) void k_mlp(
    const float* __restrict__ x, const float* __restrict__ b1,
    const float* __restrict__ b2, const float* __restrict__ gamma,
    const float* __restrict__ beta, float* __restrict__ out)
{
    extern __shared__ char sm[];
    const int t = threadIdx.x, w = t >> 5, l = t & 31;
    const int wm = w & 3, wn = w >> 2, j = l & 3;
    const uint32_t sb = smem_u32(sm);
    const int rb = blockIdx.x, rowb = rb * 128;

    // ---------------- phase 1: h1pre = z @ W1 ----------------
    #pragma unroll
    for (int i0 = 0; i0 < 4; i0++) {
        int i = i0 * 512 + t;
        cpa16(sb + P_B(0) + i * 16, g_w1H + i * 16);
        cpa16(sb + P_BL(0) + i * 16, g_w1L + i * 16);
    }
    cpa_commit();
    #pragma unroll
    for (int i0 = 0; i0 < 8; i0++) {
        int i = i0 * 512 + t;
        int r = i >> 5, kp = i & 31;
        int row = min(rowb + r, NN - 1);
        float2 v = *(const float2*)(g_z + (size_t)row * DIM + kp * 2);
        store_pair(sm + P_A(0), sm + P_AL(0), swz<7>((uint32_t)(r * 128 + kp * 4)), v);
    }

    float acc[2][8][4];
    #pragma unroll
    for (int mf = 0; mf < 2; mf++)
        #pragma unroll
        for (int nf = 0; nf < 8; nf++) {
            acc[mf][nf][0] = 0.f; acc[mf][nf][1] = 0.f;
            acc[mf][nf][2] = 0.f; acc[mf][nf][3] = 0.f;
        }

    #pragma unroll 1
    for (int c = 0; c < 4; c++) {
        cpa_wait0();
        __syncthreads();
        if (c < 3) {
            int nb = (c + 1) & 1;
            #pragma unroll
            for (int i0 = 0; i0 < 4; i0++) {
                int i = i0 * 512 + t;
                cpa16(sb + P_B(nb) + i * 16, g_w1H + (c + 1) * 32768 + i * 16);
                cpa16(sb + P_BL(nb) + i * 16, g_w1L + (c + 1) * 32768 + i * 16);
            }
            cpa_commit();
            #pragma unroll
            for (int i0 = 0; i0 < 8; i0++) {
                int i = i0 * 512 + t;
                int r = i >> 5, kp = i & 31;
                int row = min(rowb + r, NN - 1);
                float2 v = *(const float2*)(g_z + (size_t)row * DIM + (c + 1) * 64 + kp * 2);
                store_pair(sm + P_A(nb), sm + P_AL(nb),
                           swz<7>((uint32_t)(r * 128 + kp * 4)), v);
            }
        }
        int cb = c & 1;
        mma_chunk(acc, sb + P_A(cb), sb + P_AL(cb), sb + P_B(cb), sb + P_BL(cb),
                  wm * 32, wn * 64, l);
    }
    __syncthreads();   // all warps finished layer-1 mma; all buffers reusable

    // prefetch W2 chunk 0 (overlaps the h1 conversion below)
    #pragma unroll
    for (int i0 = 0; i0 < 4; i0++) {
        int i = i0 * 512 + t;
        cpa16(sb + W2HI + i * 16, g_w2H + i * 16);
        cpa16(sb + W2LO + i * 16, g_w2L + i * 16);
    }
    cpa_commit();

    // h1 = relu(acc + b1) -> bf16 hi/lo images in smem
    #pragma unroll
    for (int mf = 0; mf < 2; mf++)
        #pragma unroll
        for (int rh = 0; rh < 2; rh++) {
            int r = wm * 32 + mf * 16 + rh * 8 + (l >> 2);
            #pragma unroll
            for (int nq = 0; nq < 4; nq++) {
                int col = wn * 64 + nq * 16 + 4 * j;
                float4 bv = __ldg((const float4*)b1 + (col >> 2));
                float h0 = fmaxf(acc[mf][2 * nq][2 * rh]     + bv.x, 0.f);
                float h1 = fmaxf(acc[mf][2 * nq][2 * rh + 1] + bv.y, 0.f);
                float h2 = fmaxf(acc[mf][2 * nq + 1][2 * rh]     + bv.z, 0.f);
                float h3 = fmaxf(acc[mf][2 * nq + 1][2 * rh + 1] + bv.w, 0.f);
                __nv_bfloat16 b0 = __float2bfloat16(h0), b1v = __float2bfloat16(h1);
                __nv_bfloat16 b2v = __float2bfloat16(h2), b3 = __float2bfloat16(h3);
                __nv_bfloat16 c0 = __float2bfloat16(h0 - __bfloat162float(b0));
                __nv_bfloat16 c1 = __float2bfloat16(h1 - __bfloat162float(b1v));
                __nv_bfloat16 c2 = __float2bfloat16(h2 - __bfloat162float(b2v));
                __nv_bfloat16 c3 = __float2bfloat16(h3 - __bfloat162float(b3));
                int kc = col >> 6, kp = col & 63;
                uint32_t off = (uint32_t)H1(kc) + swz<7>((uint32_t)(r * 128 + kp * 2));
                __nv_bfloat162 hA = __halves2bfloat162(b0, b1v);
                __nv_bfloat162 hB = __halves2bfloat162(b2v, b3);
                *(ull*)(sm + off) = ((ull)*(uint32_t*)&hB << 32) | *(uint32_t*)&hA;
                __nv_bfloat162 lA = __halves2bfloat162(c0, c1);
                __nv_bfloat162 lB = __halves2bfloat162(c2, c3);
                *(ull*)(sm + off + 16384) = ((ull)*(uint32_t*)&lB << 32) | *(uint32_t*)&lA;
            }
        }

    // ---------------- phase 2: h2pre = h1 @ W2 ----------------
    #pragma unroll
    for (int mf = 0; mf < 2; mf++)
        #pragma unroll
        for (int nf = 0; nf < 8; nf++) {
            acc[mf][nf][0] = 0.f; acc[mf][nf][1] = 0.f;
            acc[mf][nf][2] = 0.f; acc[mf][nf][3] = 0.f;
        }

    #pragma unroll 1
    for (int c = 0; c < 4; c++) {
        cpa_wait0();
        __syncthreads();    // W2 chunk + (c==0: h1 images) visible
        mma_chunk(acc, sb + H1(c), sb + H1(c) + 16384, sb + W2HI, sb + W2LO,
                  wm * 32, wn * 64, l);
        __syncthreads();    // all warps done reading the W2 buffer
        if (c < 3) {
            #pragma unroll
            for (int i0 = 0; i0 < 4; i0++) {
                int i = i0 * 512 + t;
                cpa16(sb + W2HI + i * 16, g_w2H + (c + 1) * 32768 + i * 16);
                cpa16(sb + W2LO + i * 16, g_w2L + (c + 1) * 32768 + i * 16);
            }
            cpa_commit();
        }
    }

    // ---------------- epilogue: h = relu(acc+b2)+x ; LayerNorm ; out ----------
    float2* sred = (float2*)(sm + LNPART);
    #pragma unroll
    for (int mf = 0; mf < 2; mf++)
        #pragma unroll
        for (int rh = 0; rh < 2; rh++) {
            int r = wm * 32 + mf * 16 + rh * 8 + (l >> 2);
            int gcl = min(rowb + r, NN - 1);
            const float4* xr = (const float4*)(x + (size_t)gcl * DIM);
            float s = 0.f, q = 0.f;
            #pragma unroll
            for (int nq = 0; nq < 4; nq++) {
                int col = wn * 64 + nq * 16 + 4 * j;
                float4 bv = __ldg((const float4*)b2 + (col >> 2));
                float4 xv = __ldg(xr + (col >> 2));
                float h0 = fmaxf(acc[mf][2 * nq][2 * rh]     + bv.x, 0.f) + xv.x;
                float h1 = fmaxf(acc[mf][2 * nq][2 * rh + 1] + bv.y, 0.f) + xv.y;
                float h2 = fmaxf(acc[mf][2 * nq + 1][2 * rh]     + bv.z, 0.f) + xv.z;
                float h3 = fmaxf(acc[mf][2 * nq + 1][2 * rh + 1] + bv.w, 0.f) + xv.w;
                acc[mf][2 * nq][2 * rh]         = h0;
                acc[mf][2 * nq][2 * rh + 1]     = h1;
                acc[mf][2 * nq + 1][2 * rh]     = h2;
                acc[mf][2 * nq + 1][2 * rh + 1] = h3;
                s += (h0 + h1) + (h2 + h3);
                q += h0 * h0 + h1 * h1 + h2 * h2 + h3 * h3;
            }
            // reduce over the j-quad (lanes sharing this row)
            s += __shfl_xor_sync(0xffffffffu, s, 1);
            q += __shfl_xor_sync(0xffffffffu, q, 1);
            s += __shfl_xor_sync(0xffffffffu, s, 2);
            q += __shfl_xor_sync(0xffffffffu, q, 2);
            if (j == 0) sred[r * 4 + wn] = make_float2(s, q);
        }
    __syncthreads();

    #pragma unroll
    for (int mf = 0; mf < 2; mf++)
        #pragma unroll
        for (int rh = 0; rh < 2; rh++) {
            int r = wm * 32 + mf * 16 + rh * 8 + (l >> 2);
            int grow = rowb + r;
            float2 p0 = sred[r * 4 + 0], p1 = sred[r * 4 + 1];
            float2 p2 = sred[r * 4 + 2], p3 = sred[r * 4 + 3];
            float s = (p0.x + p1.x) + (p2.x + p3.x);
            float q = (p0.y + p1.y) + (p2.y + p3.y);
            float mu = s * (1.0f / 256.0f);
            float var = q * (1.0f / 256.0f) - mu * mu;
            float inv = rsqrtf(var + 1e-5f);
            if (grow < NN) {
                #pragma unroll
                for (int nq = 0; nq < 4; nq++) {
                    int col = wn * 64 + nq * 16 + 4 * j;
                    float4 gv = __ldg((const float4*)gamma + (col >> 2));
                    float4 tv = __ldg((const float4*)beta + (col >> 2));
                    float4 o;
                    o.x = (acc[mf][2 * nq][2 * rh]         - mu) * inv * gv.x + tv.x;
                    o.y = (acc[mf][2 * nq][2 * rh + 1]     - mu) * inv * gv.y + tv.y;
                    o.z = (acc[mf][2 * nq + 1][2 * rh]     - mu) * inv * gv.z + tv.z;
                    o.w = (acc[mf][2 * nq + 1][2 * rh + 1] - mu) * inv * gv.w + tv.w;
                    ((float4*)(out + (size_t)grow * DIM))[col >> 2] = o;
                }
            }
        }
}

// ---------------------------------------------------------------------------
extern "C" void kernel_launch(void* const* d_in, const int* in_sizes, int n_in,
                              void* d_out, int out_size)
{
    const float* x     = (const float*)d_in[0];
    const int*   eidx  = (const int*)d_in[1];     // int32 (JAX x64 disabled)
    const float* ea    = (const float*)d_in[2];
    const float* We    = (const float*)d_in[3];
    const float* be    = (const float*)d_in[4];
    const float* W1    = (const float*)d_in[5];
    const float* b1    = (const float*)d_in[6];
    const float* W2    = (const float*)d_in[7];
    const float* b2    = (const float*)d_in[8];
    const float* gamma = (const float*)d_in[9];
    const float* beta  = (const float*)d_in[10];
    float* out         = (float*)d_out;

    cudaFuncSetAttribute(k_edge, cudaFuncAttributeMaxDynamicSharedMemorySize, E_SMEM);
    cudaFuncSetAttribute(k_mlp, cudaFuncAttributeMaxDynamicSharedMemorySize, P_SMEM);

    k_prep<<<288, 256>>>(We, W1, W2);
    k_init<<<12500, 256>>>((const float4*)x);
    k_edge<<<6250, 256, E_SMEM>>>(x, eidx, ea, be);
    k_mlp<<<RB, 512, P_SMEM>>>(x, b1, b2, gamma, beta, out);
}